// round 5
// baseline (speedup 1.0000x reference)
#include <cuda_runtime.h>
#include <cstdint>

// Problem constants
#define BATCH 4
#define SEQ   2048
#define DMODEL 2048
#define NHEADS 16
#define HDIM  128
#define M_TOK (BATCH * SEQ)          // 8192
// softmax scale folded with log2(e):  (1/sqrt(128)) * log2(e)
#define SL2 (0.08838834764831845f * 1.4426950408889634f)

// ---------------------------------------------------------------------------
// Scratch
// ---------------------------------------------------------------------------
__device__ float g_q[M_TOK * DMODEL];
__device__ float g_k[M_TOK * DMODEL];
__device__ float g_v[M_TOK * DMODEL];
__device__ float g_attn[M_TOK * DMODEL];

// ---------------------------------------------------------------------------
// Common PTX helpers
// ---------------------------------------------------------------------------
__device__ __forceinline__ uint32_t f2tf32(float f) {
    uint32_t r;
    asm("cvt.rna.tf32.f32 %0, %1;" : "=r"(r) : "f"(f));
    return r;
}

__device__ __forceinline__ void mma_tf32(float c[4], const uint32_t a[4], const uint32_t b[2]) {
    asm volatile(
        "mma.sync.aligned.m16n8k8.row.col.f32.tf32.tf32.f32 "
        "{%0,%1,%2,%3}, {%4,%5,%6,%7}, {%8,%9}, {%0,%1,%2,%3};"
        : "+f"(c[0]), "+f"(c[1]), "+f"(c[2]), "+f"(c[3])
        : "r"(a[0]), "r"(a[1]), "r"(a[2]), "r"(a[3]), "r"(b[0]), "r"(b[1]));
}

__device__ __forceinline__ float ex2(float x) {
    float y;
    asm("ex2.approx.f32 %0, %1;" : "=f"(y) : "f"(x));
    return y;
}

__device__ __forceinline__ void cp16(float* dst_smem, const float* src_gmem) {
    uint32_t d = (uint32_t)__cvta_generic_to_shared(dst_smem);
    asm volatile("cp.async.cg.shared.global [%0], [%1], 16;" :: "r"(d), "l"(src_gmem));
}
__device__ __forceinline__ void cp_commit() {
    asm volatile("cp.async.commit_group;");
}
template<int N> __device__ __forceinline__ void cp_wait() {
    asm volatile("cp.async.wait_group %0;" :: "n"(N));
}

// ---------------------------------------------------------------------------
// TF32 tensor-core GEMM with FRAGMENT-MAJOR smem layout.
// C[M=8192, N=2048] = A[M,2048] @ W[2048, N] + bias
// CTA tile 128x128, Ktile 16, 8 warps (2x4), warp tile 64x32.
//
// smem A: [j=k8blk(2)][i=m16blk(8)][lane(32)][4]  -> lane's A-frag is one LDS.128
//   slot map: {a0=(g,t), a1=(g+8,t), a2=(g,t+4), a3=(g+8,t+4)}
// smem B: [j=k8blk(2)][nblk=n8blk(16)][lane(32)][2] -> lane's B-frag is one LDS.64
//   slot map: {b0=(k=t,n=g), b1=(k=t+4,n=g)}
// ---------------------------------------------------------------------------
#define GK DMODEL
#define GN DMODEL

__global__ __launch_bounds__(256, 2)
void gemm_tf32_kernel(const float* __restrict__ A,
                      const float* __restrict__ W,
                      const float* __restrict__ bias,
                      float* __restrict__ dst,
                      int mode)
{
    __shared__ uint32_t sA[2][2048];   // 2 k8blks * 8 m16blks * 32 lanes * 4
    __shared__ uint32_t sB[2][2048];   // 2 k8blks * 16 n8blks * 32 lanes * 2

    const int tid  = threadIdx.x;
    const int wid  = tid >> 5;
    const int lane = tid & 31;
    const int g    = lane >> 2;
    const int t    = lane & 3;

    const int bm = blockIdx.y * 128;
    const int bn = blockIdx.x * 128;

    const int warp_m = (wid >> 2) * 64;   // 0 or 64
    const int warp_n = (wid & 3) * 32;    // 0,32,64,96
    const int mi0 = warp_m >> 4;          // base m16 block
    const int nb0 = warp_n >> 3;          // base n8 block

    // ---- loader assignment ----
    // A: row = tid>>1 (0..127), kc = (tid&1)*4; pieces at kc and kc+8
    const int a_row  = tid >> 1;
    const int a_kc   = (tid & 1) * 4;
    const int a_i    = a_row >> 4;
    const int a_g    = a_row & 7;
    const int a_half = (a_row >> 3) & 1;
    // piece p (kcp = a_kc + 8p): j = kcp>>3, klo = kcp&7 (0 or 4)
    // float idx = ((j*8 + a_i)*32 + 4*a_g + e)*4 + a_half + (klo?2:0)
    int a_st[2];
#pragma unroll
    for (int p = 0; p < 2; p++) {
        const int kcp = a_kc + 8 * p;
        const int j   = kcp >> 3;
        const int klo = kcp & 7;
        a_st[p] = ((j * 8 + a_i) * 32 + 4 * a_g) * 4 + a_half + (klo ? 2 : 0);
    }

    // B: k = tid>>4 (0..15), col = (tid&15)*4; pieces at col and col+64
    const int b_k    = tid >> 4;
    const int b_col  = (tid & 15) * 4;
    const int b_j    = b_k >> 3;
    const int b_t    = b_k & 3;
    const int b_slot = ((b_k >> 2) & 1);
    int b_st[2];
#pragma unroll
    for (int p = 0; p < 2; p++) {
        const int colp = b_col + 64 * p;
        const int nblk = colp >> 3;
        const int g0   = colp & 7;     // 0 or 4
        b_st[p] = ((b_j * 16 + nblk) * 32 + 4 * g0 + b_t) * 2 + b_slot;
    }

    const float* Aptr = A + (size_t)(bm + a_row) * GK + a_kc;
    const float* Wptr = W + (size_t)b_k * GN + bn + b_col;

    float acc[4][4][4];
#pragma unroll
    for (int i = 0; i < 4; i++)
#pragma unroll
        for (int j = 0; j < 4; j++)
#pragma unroll
            for (int r = 0; r < 4; r++) acc[i][j][r] = 0.f;

    // ---- store helpers (cvt + scatter) ----
#define STORE_TILE(BUF)                                                        \
    do {                                                                       \
        uint32_t* pa = sA[BUF];                                                \
        uint32_t* pb = sB[BUF];                                                \
        pa[a_st[0] + 0]  = f2tf32(av0.x);                                      \
        pa[a_st[0] + 4]  = f2tf32(av0.y);                                      \
        pa[a_st[0] + 8]  = f2tf32(av0.z);                                      \
        pa[a_st[0] + 12] = f2tf32(av0.w);                                      \
        pa[a_st[1] + 0]  = f2tf32(av1.x);                                      \
        pa[a_st[1] + 4]  = f2tf32(av1.y);                                      \
        pa[a_st[1] + 8]  = f2tf32(av1.z);                                      \
        pa[a_st[1] + 12] = f2tf32(av1.w);                                      \
        pb[b_st[0] + 0]  = f2tf32(bv0.x);                                      \
        pb[b_st[0] + 8]  = f2tf32(bv0.y);                                      \
        pb[b_st[0] + 16] = f2tf32(bv0.z);                                      \
        pb[b_st[0] + 24] = f2tf32(bv0.w);                                      \
        pb[b_st[1] + 0]  = f2tf32(bv1.x);                                      \
        pb[b_st[1] + 8]  = f2tf32(bv1.y);                                      \
        pb[b_st[1] + 16] = f2tf32(bv1.z);                                      \
        pb[b_st[1] + 24] = f2tf32(bv1.w);                                      \
    } while (0)

    // ---- prologue: K-tile 0 -> buffer 0 ----
    {
        float4 av0 = *(const float4*)(Aptr);
        float4 av1 = *(const float4*)(Aptr + 8);
        float4 bv0 = *(const float4*)(Wptr);
        float4 bv1 = *(const float4*)(Wptr + 64);
        STORE_TILE(0);
    }
    __syncthreads();

    for (int k0 = 0; k0 < GK; k0 += 16) {
        const int cur = (k0 >> 4) & 1;
        const bool has_next = (k0 + 16) < GK;

        float4 av0, av1, bv0, bv1;
        if (has_next) {
            av0 = *(const float4*)(Aptr + k0 + 16);
            av1 = *(const float4*)(Aptr + k0 + 24);
            bv0 = *(const float4*)(Wptr + (size_t)(k0 + 16) * GN);
            bv1 = *(const float4*)(Wptr + (size_t)(k0 + 16) * GN + 64);
        }

        const uint32_t* cA = sA[cur];
        const uint32_t* cB = sB[cur];
#pragma unroll
        for (int kkb = 0; kkb < 2; kkb++) {
            uint32_t afr[4][4];
            uint32_t bfr[4][2];
#pragma unroll
            for (int mf = 0; mf < 4; mf++) {
                const uint4 v = *(const uint4*)&cA[((kkb * 8 + mi0 + mf) * 32 + lane) * 4];
                afr[mf][0] = v.x; afr[mf][1] = v.y; afr[mf][2] = v.z; afr[mf][3] = v.w;
            }
#pragma unroll
            for (int nf = 0; nf < 4; nf++) {
                const uint2 v = *(const uint2*)&cB[((kkb * 16 + nb0 + nf) * 32 + lane) * 2];
                bfr[nf][0] = v.x; bfr[nf][1] = v.y;
            }
#pragma unroll
            for (int mf = 0; mf < 4; mf++)
#pragma unroll
                for (int nf = 0; nf < 4; nf++)
                    mma_tf32(acc[mf][nf], afr[mf], bfr[nf]);
        }

        if (has_next) {
            STORE_TILE(cur ^ 1);
        }
        __syncthreads();
    }
#undef STORE_TILE

    // ---- epilogue: bias add + store ----
#pragma unroll
    for (int mf = 0; mf < 4; mf++) {
#pragma unroll
        for (int nf = 0; nf < 4; nf++) {
            const int col = bn + warp_n + 8 * nf + 2 * t;
            const float b0 = bias[col];
            const float b1 = bias[col + 1];
#pragma unroll
            for (int half = 0; half < 2; half++) {
                const int row = bm + warp_m + 16 * mf + g + 8 * half;
                float2 v;
                v.x = acc[mf][nf][2 * half + 0] + b0;
                v.y = acc[mf][nf][2 * half + 1] + b1;
                if (mode == 0) {
                    *(float2*)&dst[(size_t)row * GN + col] = v;
                } else {
                    const int b_ = row >> 11;
                    const int s_ = row & 2047;
                    const int h_ = col >> 7;
                    const int d_ = col & 127;
                    *(float2*)&dst[(((size_t)(b_ * NHEADS + h_)) * SEQ + s_) * HDIM + d_] = v;
                }
            }
        }
    }
}

// ---------------------------------------------------------------------------
// Tensor-core flash attention (tf32 mma), causal — unchanged from round 3.
// ---------------------------------------------------------------------------
#define K_ST 132
#define V_ST 136
#define Q_ST 136
#define P_ST 136

#define SM_QT_F   (128 * Q_ST)
#define SM_K_F    (2 * 64 * K_ST)
#define SM_V_F    (64 * V_ST)
#define SM_PT_F   (64 * P_ST)
#define SM_RED_F  128
#define SMA_FLOATS (SM_QT_F + SM_K_F + SM_V_F + SM_PT_F + SM_RED_F)
#define SMA_BYTES  (SMA_FLOATS * 4)

__device__ __forceinline__ void load_k_tile(float* dst, const float* src, int tid) {
#pragma unroll
    for (int j = 0; j < 8; j++) {
        int c = tid + j * 256;
        int row = c >> 5;
        int c16 = (c & 31) * 4;
        cp16(dst + row * K_ST + c16, src + (size_t)row * HDIM + c16);
    }
}
__device__ __forceinline__ void load_v_tile(float* dst, const float* src, int tid) {
#pragma unroll
    for (int j = 0; j < 8; j++) {
        int c = tid + j * 256;
        int row = c >> 5;
        int c16 = (c & 31) * 4;
        cp16(dst + row * V_ST + c16, src + (size_t)row * HDIM + c16);
    }
}

__global__ __launch_bounds__(256, 1)
void attn_mma_kernel(const float* __restrict__ Q,
                     const float* __restrict__ K,
                     const float* __restrict__ V,
                     float* __restrict__ O)
{
    extern __shared__ float sm[];
    float* sQt  = sm;
    float* sK   = sQt + SM_QT_F;
    float* sV   = sK + SM_K_F;
    float* sPT  = sV + SM_V_F;
    float* sRed = sPT + SM_PT_F;

    const int tid  = threadIdx.x;
    const int wid  = tid >> 5;
    const int lane = tid & 31;
    const int g    = lane >> 2;
    const int t    = lane & 3;
    const int qw   = 16 * wid;

    const int qb = (gridDim.x - 1) - blockIdx.x;
    const int h  = blockIdx.y;
    const int b  = blockIdx.z;

    const size_t head = ((size_t)(b * NHEADS + h)) * SEQ * HDIM;
    const float* Qb = Q + head + (size_t)qb * 128 * HDIM;
    const float* Kb = K + head;
    const float* Vb = V + head;

    for (int i = tid; i < 128 * 32; i += 256) {
        int c4 = i >> 7;
        int q  = i & 127;
        float4 v = *(const float4*)(Qb + (size_t)q * HDIM + c4 * 4);
        sQt[(4 * c4 + 0) * Q_ST + q] = __uint_as_float(f2tf32(v.x));
        sQt[(4 * c4 + 1) * Q_ST + q] = __uint_as_float(f2tf32(v.y));
        sQt[(4 * c4 + 2) * Q_ST + q] = __uint_as_float(f2tf32(v.z));
        sQt[(4 * c4 + 3) * Q_ST + q] = __uint_as_float(f2tf32(v.w));
    }

    const int ntiles = 2 * (qb + 1);

    load_k_tile(sK, Kb, tid);            cp_commit();
    load_v_tile(sV, Vb, tid);            cp_commit();

    float m_i[2][2], l_i[2][2];
    float acc_o[16][4];
#pragma unroll
    for (int nf = 0; nf < 2; nf++)
#pragma unroll
        for (int par = 0; par < 2; par++) { m_i[nf][par] = -1e30f; l_i[nf][par] = 0.f; }
#pragma unroll
    for (int i = 0; i < 16; i++)
#pragma unroll
        for (int r = 0; r < 4; r++) acc_o[i][r] = 0.f;

    __syncthreads();

    for (int kb = 0; kb < ntiles; kb++) {
        const bool has_next = (kb + 1) < ntiles;
        if (has_next) {
            load_k_tile(sK + ((kb + 1) & 1) * 64 * K_ST,
                        Kb + (size_t)(kb + 1) * 64 * HDIM, tid);
            cp_commit();
        }
        if (has_next) cp_wait<2>(); else cp_wait<1>();
        __syncthreads();

        const float* cK = sK + (kb & 1) * 64 * K_ST;
        const bool active = (kb * 64) <= (qb * 128 + qw + 15);

        float p[4][2][4];
        if (active) {
#pragma unroll
            for (int mf = 0; mf < 4; mf++)
#pragma unroll
                for (int nf = 0; nf < 2; nf++)
#pragma unroll
                    for (int r = 0; r < 4; r++) p[mf][nf][r] = 0.f;

#pragma unroll 4
            for (int kk = 0; kk < HDIM; kk += 8) {
                uint32_t afr[4][4];
#pragma unroll
                for (int mf = 0; mf < 4; mf++) {
                    const int m = 16 * mf + g;
                    afr[mf][0] = f2tf32(cK[(m)     * K_ST + kk + t]);
                    afr[mf][1] = f2tf32(cK[(m + 8) * K_ST + kk + t]);
                    afr[mf][2] = f2tf32(cK[(m)     * K_ST + kk + t + 4]);
                    afr[mf][3] = f2tf32(cK[(m + 8) * K_ST + kk + t + 4]);
                }
                uint32_t bfr[2][2];
#pragma unroll
                for (int nf = 0; nf < 2; nf++) {
                    const int qn = qw + 8 * nf + g;
                    bfr[nf][0] = __float_as_uint(sQt[(kk + t)     * Q_ST + qn]);
                    bfr[nf][1] = __float_as_uint(sQt[(kk + t + 4) * Q_ST + qn]);
                }
#pragma unroll
                for (int mf = 0; mf < 4; mf++)
#pragma unroll
                    for (int nf = 0; nf < 2; nf++)
                        mma_tf32(p[mf][nf], afr[mf], bfr[nf]);
            }

            const bool diag = (kb >= ntiles - 2);
            float mx[2][2] = {{-1e30f, -1e30f}, {-1e30f, -1e30f}};
#pragma unroll
            for (int mf = 0; mf < 4; mf++)
#pragma unroll
                for (int nf = 0; nf < 2; nf++) {
                    const int kg = kb * 64 + 16 * mf + g;
                    const int qc = qb * 128 + qw + 8 * nf + 2 * t;
#pragma unroll
                    for (int e = 0; e < 4; e++) {
                        const int kge = kg + ((e >= 2) ? 8 : 0);
                        const int qce = qc + (e & 1);
                        float v = p[mf][nf][e] * SL2;
                        if (diag && kge > qce) v = -1e30f;
                        p[mf][nf][e] = v;
                    }
                    mx[nf][0] = fmaxf(mx[nf][0], fmaxf(p[mf][nf][0], p[mf][nf][2]));
                    mx[nf][1] = fmaxf(mx[nf][1], fmaxf(p[mf][nf][1], p[mf][nf][3]));
                }
#pragma unroll
            for (int nf = 0; nf < 2; nf++)
#pragma unroll
                for (int par = 0; par < 2; par++) {
                    float v = mx[nf][par];
                    v = fmaxf(v, __shfl_xor_sync(0xffffffffu, v, 4));
                    v = fmaxf(v, __shfl_xor_sync(0xffffffffu, v, 8));
                    v = fmaxf(v, __shfl_xor_sync(0xffffffffu, v, 16));
                    mx[nf][par] = v;
                }
            float alpha[2][2];
#pragma unroll
            for (int nf = 0; nf < 2; nf++)
#pragma unroll
                for (int par = 0; par < 2; par++) {
                    const float m_new = fmaxf(m_i[nf][par], mx[nf][par]);
                    alpha[nf][par] = ex2(m_i[nf][par] - m_new);
                    m_i[nf][par] = m_new;
                }
            float sum[2][2] = {{0.f, 0.f}, {0.f, 0.f}};
#pragma unroll
            for (int mf = 0; mf < 4; mf++)
#pragma unroll
                for (int nf = 0; nf < 2; nf++) {
                    p[mf][nf][0] = ex2(p[mf][nf][0] - m_i[nf][0]);
                    p[mf][nf][1] = ex2(p[mf][nf][1] - m_i[nf][1]);
                    p[mf][nf][2] = ex2(p[mf][nf][2] - m_i[nf][0]);
                    p[mf][nf][3] = ex2(p[mf][nf][3] - m_i[nf][1]);
                    sum[nf][0] += p[mf][nf][0] + p[mf][nf][2];
                    sum[nf][1] += p[mf][nf][1] + p[mf][nf][3];
                }
#pragma unroll
            for (int nf = 0; nf < 2; nf++)
#pragma unroll
                for (int par = 0; par < 2; par++) {
                    float v = sum[nf][par];
                    v += __shfl_xor_sync(0xffffffffu, v, 4);
                    v += __shfl_xor_sync(0xffffffffu, v, 8);
                    v += __shfl_xor_sync(0xffffffffu, v, 16);
                    l_i[nf][par] = l_i[nf][par] * alpha[nf][par] + v;
                }

#pragma unroll
            for (int mf = 0; mf < 4; mf++)
#pragma unroll
                for (int nf = 0; nf < 2; nf++) {
                    const int kr = 16 * mf + g;
                    const int qc = qw + 8 * nf + 2 * t;
                    sPT[(kr)     * P_ST + qc]     = __uint_as_float(f2tf32(p[mf][nf][0]));
                    sPT[(kr)     * P_ST + qc + 1] = __uint_as_float(f2tf32(p[mf][nf][1]));
                    sPT[(kr + 8) * P_ST + qc]     = __uint_as_float(f2tf32(p[mf][nf][2]));
                    sPT[(kr + 8) * P_ST + qc + 1] = __uint_as_float(f2tf32(p[mf][nf][3]));
                }
            if (lane < 4) {
#pragma unroll
                for (int nf = 0; nf < 2; nf++)
#pragma unroll
                    for (int par = 0; par < 2; par++)
                        sRed[qw + 8 * nf + 2 * lane + par] = alpha[nf][par];
            }
            __syncwarp();
            const float al0 = sRed[qw + g];
            const float al1 = sRed[qw + g + 8];
#pragma unroll
            for (int nf2 = 0; nf2 < 16; nf2++) {
                acc_o[nf2][0] *= al0; acc_o[nf2][1] *= al0;
                acc_o[nf2][2] *= al1; acc_o[nf2][3] *= al1;
            }
        }

        if (has_next) cp_wait<1>(); else cp_wait<0>();
        __syncthreads();

        if (active) {
#pragma unroll 2
            for (int kk = 0; kk < 64; kk += 8) {
                uint32_t va[4];
                va[0] = __float_as_uint(sPT[(kk + t)     * P_ST + qw + g]);
                va[1] = __float_as_uint(sPT[(kk + t)     * P_ST + qw + g + 8]);
                va[2] = __float_as_uint(sPT[(kk + t + 4) * P_ST + qw + g]);
                va[3] = __float_as_uint(sPT[(kk + t + 4) * P_ST + qw + g + 8]);
#pragma unroll
                for (int nf2 = 0; nf2 < 16; nf2++) {
                    uint32_t vb[2];
                    vb[0] = f2tf32(sV[(kk + t)     * V_ST + 8 * nf2 + g]);
                    vb[1] = f2tf32(sV[(kk + t + 4) * V_ST + 8 * nf2 + g]);
                    mma_tf32(acc_o[nf2], va, vb);
                }
            }
        }

        __syncthreads();
        if (has_next) {
            load_v_tile(sV, Vb + (size_t)(kb + 1) * 64 * HDIM, tid);
            cp_commit();
        }
    }

    if (lane < 4) {
#pragma unroll
        for (int nf = 0; nf < 2; nf++)
#pragma unroll
            for (int par = 0; par < 2; par++)
                sRed[qw + 8 * nf + 2 * lane + par] = l_i[nf][par];
    }
    __syncwarp();
    const float il0 = 1.f / sRed[qw + g];
    const float il1 = 1.f / sRed[qw + g + 8];

    const int q0 = qb * 128 + qw + g;
    const int q1 = q0 + 8;
    const size_t base0 = ((size_t)b * SEQ + q0) * DMODEL + h * HDIM;
    const size_t base1 = ((size_t)b * SEQ + q1) * DMODEL + h * HDIM;
#pragma unroll
    for (int nf2 = 0; nf2 < 16; nf2++) {
        const int d = 8 * nf2 + 2 * t;
        float2 v0, v1;
        v0.x = acc_o[nf2][0] * il0; v0.y = acc_o[nf2][1] * il0;
        v1.x = acc_o[nf2][2] * il1; v1.y = acc_o[nf2][3] * il1;
        *(float2*)&O[base0 + d] = v0;
        *(float2*)&O[base1 + d] = v1;
    }
}

// ---------------------------------------------------------------------------
// Launch
// ---------------------------------------------------------------------------
extern "C" void kernel_launch(void* const* d_in, const int* in_sizes, int n_in,
                              void* d_out, int out_size)
{
    const float* x  = (const float*)d_in[0];
    const float* Wq = (const float*)d_in[1];
    const float* bq = (const float*)d_in[2];
    const float* Wk = (const float*)d_in[3];
    const float* bk = (const float*)d_in[4];
    const float* Wv = (const float*)d_in[5];
    const float* bv = (const float*)d_in[6];
    const float* Wo = (const float*)d_in[7];
    const float* bo = (const float*)d_in[8];
    float* out = (float*)d_out;

    float *q, *k, *v, *attn;
    cudaGetSymbolAddress((void**)&q,    g_q);
    cudaGetSymbolAddress((void**)&k,    g_k);
    cudaGetSymbolAddress((void**)&v,    g_v);
    cudaGetSymbolAddress((void**)&attn, g_attn);

    cudaFuncSetAttribute(attn_mma_kernel,
                         cudaFuncAttributeMaxDynamicSharedMemorySize, SMA_BYTES);

    dim3 gemm_grid(GN / 128, M_TOK / 128);   // (16, 64)

    gemm_tf32_kernel<<<gemm_grid, 256>>>(x, Wq, bq, q, 1);
    gemm_tf32_kernel<<<gemm_grid, 256>>>(x, Wk, bk, k, 1);
    gemm_tf32_kernel<<<gemm_grid, 256>>>(x, Wv, bv, v, 1);

    attn_mma_kernel<<<dim3(SEQ / 128, NHEADS, BATCH), 256, SMA_BYTES>>>(q, k, v, attn);

    gemm_tf32_kernel<<<gemm_grid, 256>>>(attn, Wo, bo, out, 0);
}

// round 8
// speedup vs baseline: 1.7993x; 1.7993x over previous
#include <cuda_runtime.h>
#include <cstdint>

// Problem constants
#define BATCH 4
#define SEQ   2048
#define DMODEL 2048
#define NHEADS 16
#define HDIM  128
#define M_TOK (BATCH * SEQ)          // 8192
// softmax scale folded with log2(e):  (1/sqrt(128)) * log2(e)
#define SL2 (0.08838834764831845f * 1.4426950408889634f)

// ---------------------------------------------------------------------------
// Scratch
// ---------------------------------------------------------------------------
__device__ float g_q[M_TOK * DMODEL];
__device__ float g_k[M_TOK * DMODEL];
__device__ float g_v[M_TOK * DMODEL];
__device__ float g_attn[M_TOK * DMODEL];
// tf32-prerounded copies of inputs
__device__ float g_x[M_TOK * DMODEL];
__device__ float g_wq[DMODEL * DMODEL];
__device__ float g_wk[DMODEL * DMODEL];
__device__ float g_wv[DMODEL * DMODEL];
__device__ float g_wo[DMODEL * DMODEL];

// ---------------------------------------------------------------------------
// Common PTX helpers
// ---------------------------------------------------------------------------
__device__ __forceinline__ uint32_t f2tf32(float f) {
    uint32_t r;
    asm("cvt.rna.tf32.f32 %0, %1;" : "=r"(r) : "f"(f));
    return r;
}

__device__ __forceinline__ void mma_tf32(float c[4], const uint32_t a[4], const uint32_t b[2]) {
    asm volatile(
        "mma.sync.aligned.m16n8k8.row.col.f32.tf32.tf32.f32 "
        "{%0,%1,%2,%3}, {%4,%5,%6,%7}, {%8,%9}, {%0,%1,%2,%3};"
        : "+f"(c[0]), "+f"(c[1]), "+f"(c[2]), "+f"(c[3])
        : "r"(a[0]), "r"(a[1]), "r"(a[2]), "r"(a[3]), "r"(b[0]), "r"(b[1]));
}

__device__ __forceinline__ float ex2(float x) {
    float y;
    asm("ex2.approx.f32 %0, %1;" : "=f"(y) : "f"(x));
    return y;
}

__device__ __forceinline__ void cp16(float* dst_smem, const float* src_gmem) {
    uint32_t d = (uint32_t)__cvta_generic_to_shared(dst_smem);
    asm volatile("cp.async.cg.shared.global [%0], [%1], 16;" :: "r"(d), "l"(src_gmem));
}
__device__ __forceinline__ void cp_commit() {
    asm volatile("cp.async.commit_group;");
}
template<int N> __device__ __forceinline__ void cp_wait() {
    asm volatile("cp.async.wait_group %0;" :: "n"(N));
}

// ---------------------------------------------------------------------------
// Pre-round fp32 -> tf32 bit pattern (element-wise, vectorized)
// ---------------------------------------------------------------------------
__global__ __launch_bounds__(256)
void preround_kernel(const float4* __restrict__ src, float4* __restrict__ dst, int n4)
{
    int i = blockIdx.x * 256 + threadIdx.x;
    if (i < n4) {
        float4 v = src[i];
        v.x = __uint_as_float(f2tf32(v.x));
        v.y = __uint_as_float(f2tf32(v.y));
        v.z = __uint_as_float(f2tf32(v.z));
        v.w = __uint_as_float(f2tf32(v.w));
        dst[i] = v;
    }
}

// ---------------------------------------------------------------------------
// TF32 tensor-core GEMM (round-3 smem layout, cp.async 3-stage pipeline).
// Inputs A and W must already be tf32-rounded bit patterns.
// C[M=8192, N=2048] = A @ W + bias.
// CTA tile 128x128, Ktile 16, 8 warps (2x4), warp tile 64x32.
//   sA [m][k] stride 20  (A-frag scalar LDS banks conflict-free)
//   sB [k][n] stride 136 (B-frag scalar LDS banks conflict-free)
// mode 0: plain fp32 store; mode 1: split-head store, tf32-rounded.
// ---------------------------------------------------------------------------
#define GK DMODEL
#define GN DMODEL
#define SA_ST 20
#define SB_ST 136
#define TA_F (128 * SA_ST)     // 2560 floats per A tile
#define TB_F (16 * SB_ST)      // 2176 floats per B tile
#define GEMM_SM_BYTES (3 * (TA_F + TB_F) * 4)   // 56832 B

__global__ __launch_bounds__(256, 2)
void gemm_tf32_kernel(const float* __restrict__ A,
                      const float* __restrict__ W,
                      const float* __restrict__ bias,
                      float* __restrict__ dst,
                      int mode)
{
    extern __shared__ float gsm[];
    float* sAb = gsm;                 // [3][TA_F]
    float* sBb = gsm + 3 * TA_F;      // [3][TB_F]

    const int tid  = threadIdx.x;
    const int wid  = tid >> 5;
    const int lane = tid & 31;
    const int g    = lane >> 2;
    const int t    = lane & 3;

    const int bm = blockIdx.y * 128;
    const int bn = blockIdx.x * 128;

    const int warp_m = (wid >> 2) * 64;   // 0 or 64
    const int warp_n = (wid & 3) * 32;    // 0,32,64,96

    // loader assignment
    const int a_row = tid >> 1;            // 0..127
    const int a_kc  = (tid & 1) * 4;       // 0 or 4 (second piece +8)
    const int b_row = tid >> 4;            // 0..15
    const int b_col = (tid & 15) * 4;      // 0..60 (second piece +64)

    const float* Aptr = A + (size_t)(bm + a_row) * GK + a_kc;
    const float* Wptr = W + (size_t)b_row * GN + bn + b_col;

    float acc[4][4][4];
#pragma unroll
    for (int i = 0; i < 4; i++)
#pragma unroll
        for (int j = 0; j < 4; j++)
#pragma unroll
            for (int r = 0; r < 4; r++) acc[i][j][r] = 0.f;

#define ISSUE(TI)                                                              \
    do {                                                                       \
        const int _buf = (TI) % 3;                                             \
        float* pa = sAb + _buf * TA_F;                                         \
        float* pb = sBb + _buf * TB_F;                                         \
        const int _k0 = (TI) * 16;                                             \
        cp16(pa + a_row * SA_ST + a_kc,     Aptr + _k0);                       \
        cp16(pa + a_row * SA_ST + a_kc + 8, Aptr + _k0 + 8);                   \
        cp16(pb + b_row * SB_ST + b_col,      Wptr + (size_t)_k0 * GN);        \
        cp16(pb + b_row * SB_ST + b_col + 64, Wptr + (size_t)_k0 * GN + 64);   \
        cp_commit();                                                           \
    } while (0)

    ISSUE(0);
    ISSUE(1);

    const int NT = GK / 16;   // 128
    for (int i = 0; i < NT; i++) {
        if (i + 1 < NT) cp_wait<1>(); else cp_wait<0>();
        __syncthreads();                 // tile i visible; all threads done with buf (i+2)%3
        if (i + 2 < NT) ISSUE(i + 2);    // overwrite buf (i-1)%3 — safe after sync

        const float* cA = sAb + (i % 3) * TA_F;
        const float* cB = sBb + (i % 3) * TB_F;
#pragma unroll
        for (int kk = 0; kk < 16; kk += 8) {
            uint32_t afr[4][4];
            uint32_t bfr[4][2];
#pragma unroll
            for (int mf = 0; mf < 4; mf++) {
                const int m = warp_m + 16 * mf + g;
                afr[mf][0] = __float_as_uint(cA[(m)     * SA_ST + kk + t]);
                afr[mf][1] = __float_as_uint(cA[(m + 8) * SA_ST + kk + t]);
                afr[mf][2] = __float_as_uint(cA[(m)     * SA_ST + kk + t + 4]);
                afr[mf][3] = __float_as_uint(cA[(m + 8) * SA_ST + kk + t + 4]);
            }
#pragma unroll
            for (int nf = 0; nf < 4; nf++) {
                const int n = warp_n + 8 * nf + g;
                bfr[nf][0] = __float_as_uint(cB[(kk + t)     * SB_ST + n]);
                bfr[nf][1] = __float_as_uint(cB[(kk + t + 4) * SB_ST + n]);
            }
#pragma unroll
            for (int mf = 0; mf < 4; mf++)
#pragma unroll
                for (int nf = 0; nf < 4; nf++)
                    mma_tf32(acc[mf][nf], afr[mf], bfr[nf]);
        }
    }
#undef ISSUE

    // ---- epilogue: bias add + store (mode 1: tf32-rounded split-head) ----
#pragma unroll
    for (int mf = 0; mf < 4; mf++) {
#pragma unroll
        for (int nf = 0; nf < 4; nf++) {
            const int col = bn + warp_n + 8 * nf + 2 * t;
            const float b0 = bias[col];
            const float b1 = bias[col + 1];
#pragma unroll
            for (int half = 0; half < 2; half++) {
                const int row = bm + warp_m + 16 * mf + g + 8 * half;
                float2 v;
                v.x = acc[mf][nf][2 * half + 0] + b0;
                v.y = acc[mf][nf][2 * half + 1] + b1;
                if (mode == 0) {
                    *(float2*)&dst[(size_t)row * GN + col] = v;
                } else {
                    v.x = __uint_as_float(f2tf32(v.x));
                    v.y = __uint_as_float(f2tf32(v.y));
                    const int b_ = row >> 11;
                    const int s_ = row & 2047;
                    const int h_ = col >> 7;
                    const int d_ = col & 127;
                    *(float2*)&dst[(((size_t)(b_ * NHEADS + h_)) * SEQ + s_) * HDIM + d_] = v;
                }
            }
        }
    }
}

// ---------------------------------------------------------------------------
// Tensor-core flash attention (tf32 mma), causal.
// Q/K/V arrive tf32-pre-rounded -> no cvt in hot loops.
// Output written tf32-rounded (consumed only by the tf32 Wo GEMM).
// ---------------------------------------------------------------------------
#define K_ST 132
#define V_ST 136
#define Q_ST 136
#define P_ST 136

#define SM_QT_F   (128 * Q_ST)
#define SM_K_F    (2 * 64 * K_ST)
#define SM_V_F    (64 * V_ST)
#define SM_PT_F   (64 * P_ST)
#define SM_RED_F  128
#define SMA_FLOATS (SM_QT_F + SM_K_F + SM_V_F + SM_PT_F + SM_RED_F)
#define SMA_BYTES  (SMA_FLOATS * 4)

__device__ __forceinline__ void load_k_tile(float* dst, const float* src, int tid) {
#pragma unroll
    for (int j = 0; j < 8; j++) {
        int c = tid + j * 256;
        int row = c >> 5;
        int c16 = (c & 31) * 4;
        cp16(dst + row * K_ST + c16, src + (size_t)row * HDIM + c16);
    }
}
__device__ __forceinline__ void load_v_tile(float* dst, const float* src, int tid) {
#pragma unroll
    for (int j = 0; j < 8; j++) {
        int c = tid + j * 256;
        int row = c >> 5;
        int c16 = (c & 31) * 4;
        cp16(dst + row * V_ST + c16, src + (size_t)row * HDIM + c16);
    }
}

__global__ __launch_bounds__(256, 1)
void attn_mma_kernel(const float* __restrict__ Q,
                     const float* __restrict__ K,
                     const float* __restrict__ V,
                     float* __restrict__ O)
{
    extern __shared__ float sm[];
    float* sQt  = sm;
    float* sK   = sQt + SM_QT_F;
    float* sV   = sK + SM_K_F;
    float* sPT  = sV + SM_V_F;
    float* sRed = sPT + SM_PT_F;

    const int tid  = threadIdx.x;
    const int wid  = tid >> 5;
    const int lane = tid & 31;
    const int g    = lane >> 2;
    const int t    = lane & 3;
    const int qw   = 16 * wid;

    const int qb = (gridDim.x - 1) - blockIdx.x;
    const int h  = blockIdx.y;
    const int b  = blockIdx.z;

    const size_t head = ((size_t)(b * NHEADS + h)) * SEQ * HDIM;
    const float* Qb = Q + head + (size_t)qb * 128 * HDIM;
    const float* Kb = K + head;
    const float* Vb = V + head;

    // Q already tf32-rounded: raw transpose copy
    for (int i = tid; i < 128 * 32; i += 256) {
        int c4 = i >> 7;
        int q  = i & 127;
        float4 v = *(const float4*)(Qb + (size_t)q * HDIM + c4 * 4);
        sQt[(4 * c4 + 0) * Q_ST + q] = v.x;
        sQt[(4 * c4 + 1) * Q_ST + q] = v.y;
        sQt[(4 * c4 + 2) * Q_ST + q] = v.z;
        sQt[(4 * c4 + 3) * Q_ST + q] = v.w;
    }

    const int ntiles = 2 * (qb + 1);

    load_k_tile(sK, Kb, tid);            cp_commit();
    load_v_tile(sV, Vb, tid);            cp_commit();

    float m_i[2][2], l_i[2][2];
    float acc_o[16][4];
#pragma unroll
    for (int nf = 0; nf < 2; nf++)
#pragma unroll
        for (int par = 0; par < 2; par++) { m_i[nf][par] = -1e30f; l_i[nf][par] = 0.f; }
#pragma unroll
    for (int i = 0; i < 16; i++)
#pragma unroll
        for (int r = 0; r < 4; r++) acc_o[i][r] = 0.f;

    __syncthreads();

    for (int kb = 0; kb < ntiles; kb++) {
        const bool has_next = (kb + 1) < ntiles;
        if (has_next) {
            load_k_tile(sK + ((kb + 1) & 1) * 64 * K_ST,
                        Kb + (size_t)(kb + 1) * 64 * HDIM, tid);
            cp_commit();
        }
        if (has_next) cp_wait<2>(); else cp_wait<1>();
        __syncthreads();

        const float* cK = sK + (kb & 1) * 64 * K_ST;
        const bool active = (kb * 64) <= (qb * 128 + qw + 15);

        float p[4][2][4];
        if (active) {
#pragma unroll
            for (int mf = 0; mf < 4; mf++)
#pragma unroll
                for (int nf = 0; nf < 2; nf++)
#pragma unroll
                    for (int r = 0; r < 4; r++) p[mf][nf][r] = 0.f;

            // ---- S^T = K @ Q^T (raw tf32 bit loads) ----
#pragma unroll 4
            for (int kk = 0; kk < HDIM; kk += 8) {
                uint32_t afr[4][4];
#pragma unroll
                for (int mf = 0; mf < 4; mf++) {
                    const int m = 16 * mf + g;
                    afr[mf][0] = __float_as_uint(cK[(m)     * K_ST + kk + t]);
                    afr[mf][1] = __float_as_uint(cK[(m + 8) * K_ST + kk + t]);
                    afr[mf][2] = __float_as_uint(cK[(m)     * K_ST + kk + t + 4]);
                    afr[mf][3] = __float_as_uint(cK[(m + 8) * K_ST + kk + t + 4]);
                }
                uint32_t bfr[2][2];
#pragma unroll
                for (int nf = 0; nf < 2; nf++) {
                    const int qn = qw + 8 * nf + g;
                    bfr[nf][0] = __float_as_uint(sQt[(kk + t)     * Q_ST + qn]);
                    bfr[nf][1] = __float_as_uint(sQt[(kk + t + 4) * Q_ST + qn]);
                }
#pragma unroll
                for (int mf = 0; mf < 4; mf++)
#pragma unroll
                    for (int nf = 0; nf < 2; nf++)
                        mma_tf32(p[mf][nf], afr[mf], bfr[nf]);
            }

            const bool diag = (kb >= ntiles - 2);
            float mx[2][2] = {{-1e30f, -1e30f}, {-1e30f, -1e30f}};
#pragma unroll
            for (int mf = 0; mf < 4; mf++)
#pragma unroll
                for (int nf = 0; nf < 2; nf++) {
                    const int kg = kb * 64 + 16 * mf + g;
                    const int qc = qb * 128 + qw + 8 * nf + 2 * t;
#pragma unroll
                    for (int e = 0; e < 4; e++) {
                        const int kge = kg + ((e >= 2) ? 8 : 0);
                        const int qce = qc + (e & 1);
                        float v = p[mf][nf][e] * SL2;
                        if (diag && kge > qce) v = -1e30f;
                        p[mf][nf][e] = v;
                    }
                    mx[nf][0] = fmaxf(mx[nf][0], fmaxf(p[mf][nf][0], p[mf][nf][2]));
                    mx[nf][1] = fmaxf(mx[nf][1], fmaxf(p[mf][nf][1], p[mf][nf][3]));
                }
#pragma unroll
            for (int nf = 0; nf < 2; nf++)
#pragma unroll
                for (int par = 0; par < 2; par++) {
                    float v = mx[nf][par];
                    v = fmaxf(v, __shfl_xor_sync(0xffffffffu, v, 4));
                    v = fmaxf(v, __shfl_xor_sync(0xffffffffu, v, 8));
                    v = fmaxf(v, __shfl_xor_sync(0xffffffffu, v, 16));
                    mx[nf][par] = v;
                }
            float alpha[2][2];
#pragma unroll
            for (int nf = 0; nf < 2; nf++)
#pragma unroll
                for (int par = 0; par < 2; par++) {
                    const float m_new = fmaxf(m_i[nf][par], mx[nf][par]);
                    alpha[nf][par] = ex2(m_i[nf][par] - m_new);
                    m_i[nf][par] = m_new;
                }
            float sum[2][2] = {{0.f, 0.f}, {0.f, 0.f}};
#pragma unroll
            for (int mf = 0; mf < 4; mf++)
#pragma unroll
                for (int nf = 0; nf < 2; nf++) {
                    p[mf][nf][0] = ex2(p[mf][nf][0] - m_i[nf][0]);
                    p[mf][nf][1] = ex2(p[mf][nf][1] - m_i[nf][1]);
                    p[mf][nf][2] = ex2(p[mf][nf][2] - m_i[nf][0]);
                    p[mf][nf][3] = ex2(p[mf][nf][3] - m_i[nf][1]);
                    sum[nf][0] += p[mf][nf][0] + p[mf][nf][2];
                    sum[nf][1] += p[mf][nf][1] + p[mf][nf][3];
                }
#pragma unroll
            for (int nf = 0; nf < 2; nf++)
#pragma unroll
                for (int par = 0; par < 2; par++) {
                    float v = sum[nf][par];
                    v += __shfl_xor_sync(0xffffffffu, v, 4);
                    v += __shfl_xor_sync(0xffffffffu, v, 8);
                    v += __shfl_xor_sync(0xffffffffu, v, 16);
                    l_i[nf][par] = l_i[nf][par] * alpha[nf][par] + v;
                }

            // P^T store stays tf32-rounded (P computed here)
#pragma unroll
            for (int mf = 0; mf < 4; mf++)
#pragma unroll
                for (int nf = 0; nf < 2; nf++) {
                    const int kr = 16 * mf + g;
                    const int qc = qw + 8 * nf + 2 * t;
                    sPT[(kr)     * P_ST + qc]     = __uint_as_float(f2tf32(p[mf][nf][0]));
                    sPT[(kr)     * P_ST + qc + 1] = __uint_as_float(f2tf32(p[mf][nf][1]));
                    sPT[(kr + 8) * P_ST + qc]     = __uint_as_float(f2tf32(p[mf][nf][2]));
                    sPT[(kr + 8) * P_ST + qc + 1] = __uint_as_float(f2tf32(p[mf][nf][3]));
                }
            if (lane < 4) {
#pragma unroll
                for (int nf = 0; nf < 2; nf++)
#pragma unroll
                    for (int par = 0; par < 2; par++)
                        sRed[qw + 8 * nf + 2 * lane + par] = alpha[nf][par];
            }
            __syncwarp();
            const float al0 = sRed[qw + g];
            const float al1 = sRed[qw + g + 8];
#pragma unroll
            for (int nf2 = 0; nf2 < 16; nf2++) {
                acc_o[nf2][0] *= al0; acc_o[nf2][1] *= al0;
                acc_o[nf2][2] *= al1; acc_o[nf2][3] *= al1;
            }
        }

        if (has_next) cp_wait<1>(); else cp_wait<0>();
        __syncthreads();

        if (active) {
            // ---- O += P @ V (V raw tf32 bits) ----
#pragma unroll 2
            for (int kk = 0; kk < 64; kk += 8) {
                uint32_t va[4];
                va[0] = __float_as_uint(sPT[(kk + t)     * P_ST + qw + g]);
                va[1] = __float_as_uint(sPT[(kk + t)     * P_ST + qw + g + 8]);
                va[2] = __float_as_uint(sPT[(kk + t + 4) * P_ST + qw + g]);
                va[3] = __float_as_uint(sPT[(kk + t + 4) * P_ST + qw + g + 8]);
#pragma unroll
                for (int nf2 = 0; nf2 < 16; nf2++) {
                    uint32_t vb[2];
                    vb[0] = __float_as_uint(sV[(kk + t)     * V_ST + 8 * nf2 + g]);
                    vb[1] = __float_as_uint(sV[(kk + t + 4) * V_ST + 8 * nf2 + g]);
                    mma_tf32(acc_o[nf2], va, vb);
                }
            }
        }

        __syncthreads();
        if (has_next) {
            load_v_tile(sV, Vb + (size_t)(kb + 1) * 64 * HDIM, tid);
            cp_commit();
        }
    }

    if (lane < 4) {
#pragma unroll
        for (int nf = 0; nf < 2; nf++)
#pragma unroll
            for (int par = 0; par < 2; par++)
                sRed[qw + 8 * nf + 2 * lane + par] = l_i[nf][par];
    }
    __syncwarp();
    const float il0 = 1.f / sRed[qw + g];
    const float il1 = 1.f / sRed[qw + g + 8];

    const int q0 = qb * 128 + qw + g;
    const int q1 = q0 + 8;
    const size_t base0 = ((size_t)b * SEQ + q0) * DMODEL + h * HDIM;
    const size_t base1 = ((size_t)b * SEQ + q1) * DMODEL + h * HDIM;
#pragma unroll
    for (int nf2 = 0; nf2 < 16; nf2++) {
        const int d = 8 * nf2 + 2 * t;
        float2 v0, v1;
        // output consumed only by the tf32 Wo GEMM -> pre-round here
        v0.x = __uint_as_float(f2tf32(acc_o[nf2][0] * il0));
        v0.y = __uint_as_float(f2tf32(acc_o[nf2][1] * il0));
        v1.x = __uint_as_float(f2tf32(acc_o[nf2][2] * il1));
        v1.y = __uint_as_float(f2tf32(acc_o[nf2][3] * il1));
        *(float2*)&O[base0 + d] = v0;
        *(float2*)&O[base1 + d] = v1;
    }
}

// ---------------------------------------------------------------------------
// Launch
// ---------------------------------------------------------------------------
extern "C" void kernel_launch(void* const* d_in, const int* in_sizes, int n_in,
                              void* d_out, int out_size)
{
    const float* x  = (const float*)d_in[0];
    const float* Wq = (const float*)d_in[1];
    const float* bq = (const float*)d_in[2];
    const float* Wk = (const float*)d_in[3];
    const float* bk = (const float*)d_in[4];
    const float* Wv = (const float*)d_in[5];
    const float* bv = (const float*)d_in[6];
    const float* Wo = (const float*)d_in[7];
    const float* bo = (const float*)d_in[8];
    float* out = (float*)d_out;

    float *q, *k, *v, *attn, *xr, *wq, *wk, *wv, *wo;
    cudaGetSymbolAddress((void**)&q,    g_q);
    cudaGetSymbolAddress((void**)&k,    g_k);
    cudaGetSymbolAddress((void**)&v,    g_v);
    cudaGetSymbolAddress((void**)&attn, g_attn);
    cudaGetSymbolAddress((void**)&xr,   g_x);
    cudaGetSymbolAddress((void**)&wq,   g_wq);
    cudaGetSymbolAddress((void**)&wk,   g_wk);
    cudaGetSymbolAddress((void**)&wv,   g_wv);
    cudaGetSymbolAddress((void**)&wo,   g_wo);

    cudaFuncSetAttribute(attn_mma_kernel,
                         cudaFuncAttributeMaxDynamicSharedMemorySize, SMA_BYTES);
    cudaFuncSetAttribute(gemm_tf32_kernel,
                         cudaFuncAttributeMaxDynamicSharedMemorySize, GEMM_SM_BYTES);

    // pre-round inputs to tf32 bit patterns
    const int n4x = M_TOK * DMODEL / 4;
    const int n4w = DMODEL * DMODEL / 4;
    preround_kernel<<<n4x / 256, 256>>>((const float4*)x,  (float4*)xr, n4x);
    preround_kernel<<<n4w / 256, 256>>>((const float4*)Wq, (float4*)wq, n4w);
    preround_kernel<<<n4w / 256, 256>>>((const float4*)Wk, (float4*)wk, n4w);
    preround_kernel<<<n4w / 256, 256>>>((const float4*)Wv, (float4*)wv, n4w);
    preround_kernel<<<n4w / 256, 256>>>((const float4*)Wo, (float4*)wo, n4w);

    dim3 gemm_grid(GN / 128, M_TOK / 128);   // (16, 64)

    gemm_tf32_kernel<<<gemm_grid, 256, GEMM_SM_BYTES>>>(xr, wq, bq, q, 1);
    gemm_tf32_kernel<<<gemm_grid, 256, GEMM_SM_BYTES>>>(xr, wk, bk, k, 1);
    gemm_tf32_kernel<<<gemm_grid, 256, GEMM_SM_BYTES>>>(xr, wv, bv, v, 1);

    attn_mma_kernel<<<dim3(SEQ / 128, NHEADS, BATCH), 256, SMA_BYTES>>>(q, k, v, attn);

    gemm_tf32_kernel<<<gemm_grid, 256, GEMM_SM_BYTES>>>(attn, wo, bo, out, 0);
}